// round 1
// baseline (speedup 1.0000x reference)
#include <cuda_runtime.h>
#include <cuda_bf16.h>
#include <cstdint>

// ---------------- problem constants ----------------
constexpr int T_ = 64, N_ = 40, D_ = 4, H_ = 256, R_ = 64;
constexpr int E_ = N_ * (N_ - 1);        // 1560
constexpr int TE = T_ * E_;              // 99840  (divisible by 128)
constexpr int TN = T_ * N_;              // 2560   (divisible by 128)

// ---------------- scratch (device globals; allocation-free) ----------------
__device__ float g_h1[TN * H_];
__device__ float g_nbuf[TN * H_];
__device__ float g_nsum[TN * H_];
__device__ float g_n3[TN * H_];
__device__ float g_e2[TE * H_];     // mlp2 out == skip
__device__ float g_tmp[TE * H_];    // big intermediate
__device__ float g_e4[TE * H_];     // mlp4 out (LSTM input)
__device__ float g_gf[TE * H_];     // fwd x@Wih^T + biases
__device__ float g_gr[TE * H_];     // rev
__device__ float g_hf[TE * R_];
__device__ float g_hr[TE * R_];
__device__ int   g_rlist[N_ * (N_ - 1)];

__device__ __forceinline__ float eluf(float v) { return v > 0.f ? v : expm1f(v); }
__device__ __forceinline__ float sigmf(float v) { return 1.f / (1.f + expf(-v)); }

// ---------------- mlp1 fc1 (K=4, tiny) ----------------
__global__ void mlp1_fc1(const float* __restrict__ x, const float* __restrict__ W1,
                         const float* __restrict__ b1, float* __restrict__ out) {
    int idx = blockIdx.x * blockDim.x + threadIdx.x;   // over TN*H
    int row = idx >> 8;
    int j = idx & 255;
    const float* xr = x + row * D_;
    const float* w = W1 + j * D_;
    float v = b1[j] + xr[0] * w[0] + xr[1] * w[1] + xr[2] * w[2] + xr[3] * w[3];
    out[idx] = eluf(v);
}

// ---------------- build per-node incoming edge lists ----------------
__global__ void build_rlist(const int* __restrict__ recv) {
    __shared__ int cnt;
    int n = blockIdx.x;
    if (threadIdx.x == 0) cnt = 0;
    __syncthreads();
    for (int e = threadIdx.x; e < E_; e += blockDim.x) {
        if (recv[e] == n) {
            int p = atomicAdd(&cnt, 1);
            g_rlist[n * (N_ - 1) + p] = e;
        }
    }
}

// ---------------- edge2node scatter-add (as gather-sum) ----------------
__global__ void edge2node(const float* __restrict__ e2, float* __restrict__ nsum) {
    int b = blockIdx.x;            // t*N + n
    int t = b / N_;
    int n = b - t * N_;
    int c = threadIdx.x;
    const int* lst = g_rlist + n * (N_ - 1);
    float s = 0.f;
#pragma unroll 13
    for (int i = 0; i < N_ - 1; i++) {
        int e = lst[i];
        s += e2[((size_t)t * E_ + e) * H_ + c];
    }
    nsum[(size_t)b * H_ + c] = s;
}

// ---------------- generic NT GEMM with fused gather + bias + ELU ----------------
// C[m, 0..255] = act( sum_k A[m,k] * W[n,k] + bias[n] (+ bias2[n]) )
// MODE 0: A plain [M,Kd]
// MODE 1: Kd=512:  k<256 -> src0[(t*N+send[e])*256 + k], else src0[.. recv ..]
// MODE 2: Kd=768:  seg0 src0[send], seg1 src0[recv], seg2 src1[m*256 + ..]
template <int MODE, int ACT, bool BIAS2>
__global__ __launch_bounds__(256) void gemm_nt(
    const float* __restrict__ A, const float* __restrict__ W,
    const float* __restrict__ bias, const float* __restrict__ bias2,
    float* __restrict__ C, int M, int Kd,
    const int* __restrict__ send, const int* __restrict__ recv,
    const float* __restrict__ src0, const float* __restrict__ src1) {
    __shared__ float As[16][128];
    __shared__ float Ws[16][128];

    const int bm = blockIdx.y * 128;
    const int bn = blockIdx.x * 128;
    const int tid = threadIdx.x;
    const int lr = tid >> 2;           // 0..63
    const int lk = (tid & 3) << 2;     // 0,4,8,12

    const float* abase[2][3];
#pragma unroll
    for (int rr = 0; rr < 2; rr++) {
        int m = bm + lr + rr * 64;
        if (MODE == 0) {
            abase[rr][0] = A + (size_t)m * Kd;
            abase[rr][1] = nullptr; abase[rr][2] = nullptr;
        } else {
            int t = m / E_;
            int e = m - t * E_;
            int s = send[e], r = recv[e];
            abase[rr][0] = src0 + ((size_t)t * N_ + s) * H_;
            abase[rr][1] = src0 + ((size_t)t * N_ + r) * H_;
            abase[rr][2] = (MODE == 2) ? (src1 + (size_t)m * H_) : nullptr;
        }
    }
    const float* wbase[2];
    wbase[0] = W + (size_t)(bn + lr) * Kd;
    wbase[1] = W + (size_t)(bn + lr + 64) * Kd;

    const int tx = tid & 15;
    const int ty = tid >> 4;

    float acc[8][8];
#pragma unroll
    for (int i = 0; i < 8; i++)
#pragma unroll
        for (int j = 0; j < 8; j++) acc[i][j] = 0.f;

    for (int k0 = 0; k0 < Kd; k0 += 16) {
#pragma unroll
        for (int rr = 0; rr < 2; rr++) {
            const float* p;
            if (MODE == 0) {
                p = abase[rr][0] + k0 + lk;
            } else {
                int kg = k0 + lk;
                int seg = kg >> 8;
                p = abase[rr][seg] + (kg & 255);
            }
            float4 v = *(const float4*)p;
            int row = lr + rr * 64;
            As[lk + 0][row] = v.x; As[lk + 1][row] = v.y;
            As[lk + 2][row] = v.z; As[lk + 3][row] = v.w;
            float4 w = *(const float4*)(wbase[rr] + k0 + lk);
            Ws[lk + 0][row] = w.x; Ws[lk + 1][row] = w.y;
            Ws[lk + 2][row] = w.z; Ws[lk + 3][row] = w.w;
        }
        __syncthreads();
#pragma unroll
        for (int kk = 0; kk < 16; kk++) {
            float4 a0 = *(const float4*)&As[kk][ty * 8];
            float4 a1 = *(const float4*)&As[kk][ty * 8 + 4];
            float4 b0 = *(const float4*)&Ws[kk][tx * 8];
            float4 b1 = *(const float4*)&Ws[kk][tx * 8 + 4];
            float a[8] = {a0.x, a0.y, a0.z, a0.w, a1.x, a1.y, a1.z, a1.w};
            float b[8] = {b0.x, b0.y, b0.z, b0.w, b1.x, b1.y, b1.z, b1.w};
#pragma unroll
            for (int i = 0; i < 8; i++)
#pragma unroll
                for (int j = 0; j < 8; j++)
                    acc[i][j] = fmaf(a[i], b[j], acc[i][j]);
        }
        __syncthreads();
    }

    // epilogue
    float bv[8];
#pragma unroll
    for (int j = 0; j < 8; j++) {
        int n = bn + tx * 8 + j;
        bv[j] = bias[n] + (BIAS2 ? bias2[n] : 0.f);
    }
#pragma unroll
    for (int i = 0; i < 8; i++) {
        int m = bm + ty * 8 + i;
        float* crow = C + (size_t)m * 256 + bn + tx * 8;
        float out[8];
#pragma unroll
        for (int j = 0; j < 8; j++) {
            float v = acc[i][j] + bv[j];
            out[j] = (ACT == 1) ? eluf(v) : v;
        }
        *(float4*)(crow + 0) = make_float4(out[0], out[1], out[2], out[3]);
        *(float4*)(crow + 4) = make_float4(out[4], out[5], out[6], out[7]);
    }
}

// ---------------- fused bidirectional LSTM (recurrence only) ----------------
// gates buffers hold x@Wih^T + bih + bhh. One block = 64 threads = 8 edges.
// Thread j owns cells (i,f,g,o)[j] for 8 edges. Whh quad-packed for LDS.128.
constexpr int LSTM_GROUPS = E_ / 8;            // 195 per direction
constexpr int LSTM_SMEM = 64 * 256 * 4 + 64 * 8 * 4;  // 67584 B

__global__ __launch_bounds__(64) void lstm_kernel(
    const float* __restrict__ gf, const float* __restrict__ gr,
    const float* __restrict__ fWhh, const float* __restrict__ rWhh,
    float* __restrict__ hfOut, float* __restrict__ hrOut) {
    extern __shared__ float sm[];
    float* Wq = sm;                       // [64 k][64 j][4 q] : Wq[k*256+j*4+q] = Whh[(q*64+j)*64+k]
    float4* hsm4 = (float4*)(sm + 64 * 256);  // [64 k][2] float4 = h of 8 edges at cell k

    int dir; int grp;
    const float* gates; const float* Whh; float* hout;
    if (blockIdx.x < LSTM_GROUPS) {
        dir = 0; grp = blockIdx.x; gates = gf; Whh = fWhh; hout = hfOut;
    } else {
        dir = 1; grp = blockIdx.x - LSTM_GROUPS; gates = gr; Whh = rWhh; hout = hrOut;
    }
    const int j = threadIdx.x;

    // load Wq: coalesced smem writes, scattered (L2-cached) global reads
    for (int idx = j; idx < 64 * 256; idx += 64) {
        int k = idx >> 8;
        int rem = idx & 255;
        int jj = rem >> 2;
        int q = rem & 3;
        Wq[idx] = Whh[(q * 64 + jj) * 64 + k];
    }
    for (int i = j; i < 128; i += 64) hsm4[i] = make_float4(0.f, 0.f, 0.f, 0.f);

    const int e0 = grp * 8;
    float c[8];
#pragma unroll
    for (int e = 0; e < 8; e++) c[e] = 0.f;
    __syncthreads();

    for (int s = 0; s < T_; s++) {
        int t = dir ? (T_ - 1 - s) : s;
        float a0[8], a1[8], a2[8], a3[8];
#pragma unroll
        for (int e = 0; e < 8; e++) {
            const float* gp = gates + ((size_t)t * E_ + e0 + e) * 256;
            a0[e] = gp[j]; a1[e] = gp[64 + j]; a2[e] = gp[128 + j]; a3[e] = gp[192 + j];
        }
#pragma unroll 16
        for (int k = 0; k < 64; k++) {
            float4 w  = *(const float4*)&Wq[k * 256 + j * 4];
            float4 hA = hsm4[k * 2 + 0];
            float4 hB = hsm4[k * 2 + 1];
            float hv[8] = {hA.x, hA.y, hA.z, hA.w, hB.x, hB.y, hB.z, hB.w};
#pragma unroll
            for (int e = 0; e < 8; e++) {
                a0[e] = fmaf(hv[e], w.x, a0[e]);
                a1[e] = fmaf(hv[e], w.y, a1[e]);
                a2[e] = fmaf(hv[e], w.z, a2[e]);
                a3[e] = fmaf(hv[e], w.w, a3[e]);
            }
        }
        __syncthreads();   // all reads of old h complete
        float hn[8];
#pragma unroll
        for (int e = 0; e < 8; e++) {
            float iv = sigmf(a0[e]);
            float fv = sigmf(a1[e]);
            float gv = tanhf(a2[e]);
            float ov = sigmf(a3[e]);
            c[e] = fv * c[e] + iv * gv;
            hn[e] = ov * tanhf(c[e]);
        }
        hsm4[j * 2 + 0] = make_float4(hn[0], hn[1], hn[2], hn[3]);
        hsm4[j * 2 + 1] = make_float4(hn[4], hn[5], hn[6], hn[7]);
#pragma unroll
        for (int e = 0; e < 8; e++)
            hout[((size_t)t * E_ + e0 + e) * 64 + j] = hn[e];
        __syncthreads();
    }
}

// ---------------- output projection ----------------
__global__ void out_proj(const float* __restrict__ hf, const float* __restrict__ hr,
                         const float* __restrict__ priW, const float* __restrict__ prib,
                         const float* __restrict__ encW, const float* __restrict__ encb,
                         float* __restrict__ out) {
    int m = blockIdx.x * blockDim.x + threadIdx.x;
    if (m >= TE) return;
    const float* f = hf + (size_t)m * 64;
    const float* r = hr + (size_t)m * 64;
    float p0 = prib[0], p1 = prib[1], e0 = encb[0], e1 = encb[1];
#pragma unroll 8
    for (int k = 0; k < 64; k++) {
        float fv = f[k];
        p0 = fmaf(fv, priW[k], p0);
        p1 = fmaf(fv, priW[64 + k], p1);
        e0 = fmaf(fv, encW[k], e0);
        e1 = fmaf(fv, encW[128 + k], e1);
    }
#pragma unroll 8
    for (int k = 0; k < 64; k++) {
        float rv = r[k];
        e0 = fmaf(rv, encW[64 + k], e0);
        e1 = fmaf(rv, encW[192 + k], e1);
    }
    float4 o = make_float4(p0, p1, e0, e1);
    *(float4*)(out + (size_t)m * 4) = o;
}

// ---------------- host launch ----------------
extern "C" void kernel_launch(void* const* d_in, const int* in_sizes, int n_in,
                              void* d_out, int out_size) {
    const float* x     = (const float*)d_in[0];
    const int* send    = (const int*)d_in[2];
    const int* recv    = (const int*)d_in[3];
    const float* m1W1 = (const float*)d_in[4],  *m1b1 = (const float*)d_in[5];
    const float* m1W2 = (const float*)d_in[6],  *m1b2 = (const float*)d_in[7];
    const float* m2W1 = (const float*)d_in[8],  *m2b1 = (const float*)d_in[9];
    const float* m2W2 = (const float*)d_in[10], *m2b2 = (const float*)d_in[11];
    const float* m3W1 = (const float*)d_in[12], *m3b1 = (const float*)d_in[13];
    const float* m3W2 = (const float*)d_in[14], *m3b2 = (const float*)d_in[15];
    const float* m4W1 = (const float*)d_in[16], *m4b1 = (const float*)d_in[17];
    const float* m4W2 = (const float*)d_in[18], *m4b2 = (const float*)d_in[19];
    const float* fWih = (const float*)d_in[20], *fWhh = (const float*)d_in[21];
    const float* fbih = (const float*)d_in[22], *fbhh = (const float*)d_in[23];
    const float* rWih = (const float*)d_in[24], *rWhh = (const float*)d_in[25];
    const float* rbih = (const float*)d_in[26], *rbhh = (const float*)d_in[27];
    const float* encW = (const float*)d_in[28], *encb = (const float*)d_in[29];
    const float* priW = (const float*)d_in[30], *prib = (const float*)d_in[31];

    float *d_h1, *d_nbuf, *d_nsum, *d_n3, *d_e2, *d_tmp, *d_e4, *d_gf, *d_gr, *d_hf, *d_hr;
    cudaGetSymbolAddress((void**)&d_h1,   g_h1);
    cudaGetSymbolAddress((void**)&d_nbuf, g_nbuf);
    cudaGetSymbolAddress((void**)&d_nsum, g_nsum);
    cudaGetSymbolAddress((void**)&d_n3,   g_n3);
    cudaGetSymbolAddress((void**)&d_e2,   g_e2);
    cudaGetSymbolAddress((void**)&d_tmp,  g_tmp);
    cudaGetSymbolAddress((void**)&d_e4,   g_e4);
    cudaGetSymbolAddress((void**)&d_gf,   g_gf);
    cudaGetSymbolAddress((void**)&d_gr,   g_gr);
    cudaGetSymbolAddress((void**)&d_hf,   g_hf);
    cudaGetSymbolAddress((void**)&d_hr,   g_hr);

    cudaFuncSetAttribute(lstm_kernel, cudaFuncAttributeMaxDynamicSharedMemorySize, LSTM_SMEM);

    // edge list for scatter-add
    build_rlist<<<N_, 256>>>(recv);

    // mlp1
    mlp1_fc1<<<TN * H_ / 256, 256>>>(x, m1W1, m1b1, d_nbuf);
    gemm_nt<0, 1, false><<<dim3(2, TN / 128), 256>>>(d_nbuf, m1W2, m1b2, nullptr, d_h1,
                                                     TN, H_, nullptr, nullptr, nullptr, nullptr);
    // mlp2 (fused node2edge gather)
    gemm_nt<1, 1, false><<<dim3(2, TE / 128), 256>>>(nullptr, m2W1, m2b1, nullptr, d_tmp,
                                                     TE, 2 * H_, send, recv, d_h1, nullptr);
    gemm_nt<0, 1, false><<<dim3(2, TE / 128), 256>>>(d_tmp, m2W2, m2b2, nullptr, d_e2,
                                                     TE, H_, nullptr, nullptr, nullptr, nullptr);
    // edge2node + mlp3
    edge2node<<<TN, 256>>>(d_e2, d_nsum);
    gemm_nt<0, 1, false><<<dim3(2, TN / 128), 256>>>(d_nsum, m3W1, m3b1, nullptr, d_nbuf,
                                                     TN, H_, nullptr, nullptr, nullptr, nullptr);
    gemm_nt<0, 1, false><<<dim3(2, TN / 128), 256>>>(d_nbuf, m3W2, m3b2, nullptr, d_n3,
                                                     TN, H_, nullptr, nullptr, nullptr, nullptr);
    // mlp4 (fused gather: n[send], n[recv], skip)
    gemm_nt<2, 1, false><<<dim3(2, TE / 128), 256>>>(nullptr, m4W1, m4b1, nullptr, d_tmp,
                                                     TE, 3 * H_, send, recv, d_n3, d_e2);
    gemm_nt<0, 1, false><<<dim3(2, TE / 128), 256>>>(d_tmp, m4W2, m4b2, nullptr, d_e4,
                                                     TE, H_, nullptr, nullptr, nullptr, nullptr);
    // LSTM input projections (time-parallel), biases folded
    gemm_nt<0, 0, true><<<dim3(2, TE / 128), 256>>>(d_e4, fWih, fbih, fbhh, d_gf,
                                                    TE, H_, nullptr, nullptr, nullptr, nullptr);
    gemm_nt<0, 0, true><<<dim3(2, TE / 128), 256>>>(d_e4, rWih, rbih, rbhh, d_gr,
                                                    TE, H_, nullptr, nullptr, nullptr, nullptr);
    // recurrence, both directions concurrently
    lstm_kernel<<<2 * LSTM_GROUPS, 64, LSTM_SMEM>>>(d_gf, d_gr, fWhh, rWhh, d_hf, d_hr);
    // outputs
    out_proj<<<TE / 256, 256>>>(d_hf, d_hr, priW, prib, encW, encb, (float*)d_out);
}

// round 3
// speedup vs baseline: 1.6859x; 1.6859x over previous
#include <cuda_runtime.h>
#include <cuda_bf16.h>
#include <cstdint>

// ---------------- problem constants ----------------
constexpr int T_ = 64, N_ = 40, D_ = 4, H_ = 256, R_ = 64;
constexpr int E_ = N_ * (N_ - 1);        // 1560
constexpr int TE = T_ * E_;              // 99840  (divisible by 128)
constexpr int TN = T_ * N_;              // 2560   (divisible by 128)

// ---------------- scratch (device globals; allocation-free) ----------------
__device__ float g_h1[TN * H_];
__device__ float g_nbuf[TN * H_];
__device__ float g_nsum[TN * H_];
__device__ float g_n3[TN * H_];
__device__ float g_e2[TE * H_];     // mlp2 out == skip
__device__ float g_tmp[TE * H_];    // big intermediate
__device__ float g_e4[TE * H_];     // mlp4 out (LSTM input)
__device__ float g_gf[TE * H_];     // fwd x@Wih^T + biases
__device__ float g_gr[TE * H_];     // rev
__device__ float g_hf[TE * R_];
__device__ float g_hr[TE * R_];
__device__ int   g_rlist[N_ * (N_ - 1)];

__device__ __forceinline__ float eluf(float v) { return v > 0.f ? v : expm1f(v); }
__device__ __forceinline__ float sigmf(float v) { return 1.f / (1.f + expf(-v)); }

// split (x0,x1) into bf16x2 hi and bf16x2 lo (residual)
__device__ __forceinline__ void bsplit2(float x0, float x1, uint32_t& hi, uint32_t& lo) {
    asm("cvt.rn.bf16x2.f32 %0, %1, %2;" : "=r"(hi) : "f"(x1), "f"(x0));
    __nv_bfloat162 h = *reinterpret_cast<__nv_bfloat162*>(&hi);
    float r0 = x0 - __bfloat162float(h.x);
    float r1 = x1 - __bfloat162float(h.y);
    asm("cvt.rn.bf16x2.f32 %0, %1, %2;" : "=r"(lo) : "f"(r1), "f"(r0));
}

__device__ __forceinline__ void mma_bf16(float* d, const uint32_t* a, const uint32_t* b) {
    asm volatile(
        "mma.sync.aligned.m16n8k16.row.col.f32.bf16.bf16.f32 "
        "{%0,%1,%2,%3},{%4,%5,%6,%7},{%8,%9},{%0,%1,%2,%3};"
        : "+f"(d[0]), "+f"(d[1]), "+f"(d[2]), "+f"(d[3])
        : "r"(a[0]), "r"(a[1]), "r"(a[2]), "r"(a[3]), "r"(b[0]), "r"(b[1]));
}

// ---------------- mlp1 fc1 (K=4, tiny) ----------------
__global__ void mlp1_fc1(const float* __restrict__ x, const float* __restrict__ W1,
                         const float* __restrict__ b1, float* __restrict__ out) {
    int idx = blockIdx.x * blockDim.x + threadIdx.x;   // over TN*H
    int row = idx >> 8;
    int j = idx & 255;
    const float* xr = x + row * D_;
    const float* w = W1 + j * D_;
    float v = b1[j] + xr[0] * w[0] + xr[1] * w[1] + xr[2] * w[2] + xr[3] * w[3];
    out[idx] = eluf(v);
}

// ---------------- build per-node incoming edge lists (deterministic) ----------------
__global__ void build_rlist(const int* __restrict__ recv) {
    int n = threadIdx.x;
    if (n >= N_) return;
    int p = 0;
    for (int e = 0; e < E_; e++)
        if (recv[e] == n) g_rlist[n * (N_ - 1) + p++] = e;
}

// ---------------- edge2node scatter-add (as gather-sum) ----------------
__global__ void edge2node(const float* __restrict__ e2, float* __restrict__ nsum) {
    int b = blockIdx.x;            // t*N + n
    int t = b / N_;
    int n = b - t * N_;
    int c = threadIdx.x;
    const int* lst = g_rlist + n * (N_ - 1);
    float s = 0.f;
#pragma unroll 13
    for (int i = 0; i < N_ - 1; i++) {
        int e = lst[i];
        s += e2[((size_t)t * E_ + e) * H_ + c];
    }
    nsum[(size_t)b * H_ + c] = s;
}

// ------------- tensor-core NT GEMM (bf16x3 split precision) + fused gather -------------
// C[m, 0..255] = act( sum_k A[m,k] * W[n,k] + bias[n] (+ bias2[n]) )
// MODE 0: A plain [M,Kd]
// MODE 1: Kd=512:  k<256 -> src0[(t*N+send[e])*256+k], else src0[.. recv ..]
// MODE 2: Kd=768:  seg0 src0[send], seg1 src0[recv], seg2 src1[m*256 + ..]
// Block tile 128x128, 8 warps of 64x32, k-step 16.
// smem: bf16x2-packed k-major, row stride 9 words (conflict-free for frag LDS).
constexpr int SMSB = 9;

template <int MODE, int ACT, bool BIAS2>
__global__ __launch_bounds__(256, 2) void gemm_tc(
    const float* __restrict__ A, const float* __restrict__ W,
    const float* __restrict__ bias, const float* __restrict__ bias2,
    float* __restrict__ C, int M, int Kd,
    const int* __restrict__ send, const int* __restrict__ recv,
    const float* __restrict__ src0, const float* __restrict__ src1) {
    __shared__ uint32_t sAhi[128 * SMSB], sAlo[128 * SMSB];
    __shared__ uint32_t sWhi[128 * SMSB], sWlo[128 * SMSB];

    const int tid = threadIdx.x;
    const int bm = blockIdx.y * 128;
    const int bn = blockIdx.x * 128;
    const int lr = tid >> 1;            // 0..127 : row within tile
    const int kw = (tid & 1) * 4;       // word offset within row (k offset = kw*2)
    const int k4 = kw * 2;              // float k offset: 0 or 8

    const float* arow0 = nullptr;
    const float* arow1 = nullptr;
    const float* arow2 = nullptr;
    {
        int m = bm + lr;
        if (MODE == 0) {
            arow0 = A + (size_t)m * Kd;
        } else {
            int t = m / E_;
            int e = m - t * E_;
            arow0 = src0 + ((size_t)t * N_ + send[e]) * H_;
            arow1 = src0 + ((size_t)t * N_ + recv[e]) * H_;
            if (MODE == 2) arow2 = src1 + (size_t)m * H_;
        }
    }
    const float* wrow = W + (size_t)(bn + lr) * Kd;

    const int warp = tid >> 5, lane = tid & 31;
    const int wm = (warp >> 2) * 64;    // 0 / 64
    const int wn = (warp & 3) * 32;     // 0 / 32 / 64 / 96
    const int grp = lane >> 2, q = lane & 3;

    float acc[4][4][4] = {};

    float4 va0, va1, vw0, vw1;
    auto load_a = [&](int kt) {
        if (MODE == 0) {
            va0 = *(const float4*)(arow0 + kt + k4);
            va1 = *(const float4*)(arow0 + kt + k4 + 4);
        } else {
            int kg = kt + k4;
            const float* p;
            if (MODE == 1) {
                p = (kg < 256 ? arow0 : arow1) + (kg & 255);
            } else {
                p = (kg < 256 ? arow0 : (kg < 512 ? arow1 : arow2)) + (kg & 255);
            }
            va0 = *(const float4*)p;
            va1 = *(const float4*)(p + 4);
        }
        vw0 = *(const float4*)(wrow + kt + k4);
        vw1 = *(const float4*)(wrow + kt + k4 + 4);
    };

    load_a(0);

    const int nsteps = Kd >> 4;
    for (int step = 0; step < nsteps; step++) {
        __syncthreads();   // previous iteration's fragment LDS complete
        {
            uint32_t* pah = &sAhi[lr * SMSB + kw];
            uint32_t* pal = &sAlo[lr * SMSB + kw];
            bsplit2(va0.x, va0.y, pah[0], pal[0]);
            bsplit2(va0.z, va0.w, pah[1], pal[1]);
            bsplit2(va1.x, va1.y, pah[2], pal[2]);
            bsplit2(va1.z, va1.w, pah[3], pal[3]);
            uint32_t* pwh = &sWhi[lr * SMSB + kw];
            uint32_t* pwl = &sWlo[lr * SMSB + kw];
            bsplit2(vw0.x, vw0.y, pwh[0], pwl[0]);
            bsplit2(vw0.z, vw0.w, pwh[1], pwl[1]);
            bsplit2(vw1.x, vw1.y, pwh[2], pwl[2]);
            bsplit2(vw1.z, vw1.w, pwh[3], pwl[3]);
        }
        __syncthreads();

        // issue next tile's global loads early (overlap with MMA phase)
        if (step + 1 < nsteps) load_a((step + 1) << 4);

        // B fragments for all 4 n-tiles
        uint32_t bh[4][2], bl[4][2];
#pragma unroll
        for (int nf = 0; nf < 4; nf++) {
            int c = (wn + nf * 8 + grp) * SMSB + q;
            bh[nf][0] = sWhi[c]; bh[nf][1] = sWhi[c + 4];
            bl[nf][0] = sWlo[c]; bl[nf][1] = sWlo[c + 4];
        }
#pragma unroll
        for (int mf = 0; mf < 4; mf++) {
            int r0 = (wm + mf * 16 + grp) * SMSB + q;
            int r1 = r0 + 8 * SMSB;
            uint32_t ah[4] = {sAhi[r0], sAhi[r1], sAhi[r0 + 4], sAhi[r1 + 4]};
            uint32_t al[4] = {sAlo[r0], sAlo[r1], sAlo[r0 + 4], sAlo[r1 + 4]};
#pragma unroll
            for (int nf = 0; nf < 4; nf++) {
                mma_bf16(acc[mf][nf], ah, bh[nf]);   // hi*hi
                mma_bf16(acc[mf][nf], ah, bl[nf]);   // hi*lo
                mma_bf16(acc[mf][nf], al, bh[nf]);   // lo*hi
            }
        }
    }

    // ---- epilogue: bias (+bias2), activation, float2 stores ----
    float bv0[4], bv1[4];
#pragma unroll
    for (int nf = 0; nf < 4; nf++) {
        int n = bn + wn + nf * 8 + 2 * q;
        bv0[nf] = bias[n] + (BIAS2 ? bias2[n] : 0.f);
        bv1[nf] = bias[n + 1] + (BIAS2 ? bias2[n + 1] : 0.f);
    }
#pragma unroll
    for (int mf = 0; mf < 4; mf++) {
        int r0 = bm + wm + mf * 16 + grp;
        int r1 = r0 + 8;
#pragma unroll
        for (int nf = 0; nf < 4; nf++) {
            int col = bn + wn + nf * 8 + 2 * q;
            float x0 = acc[mf][nf][0] + bv0[nf];
            float x1 = acc[mf][nf][1] + bv1[nf];
            float x2 = acc[mf][nf][2] + bv0[nf];
            float x3 = acc[mf][nf][3] + bv1[nf];
            if (ACT == 1) { x0 = eluf(x0); x1 = eluf(x1); x2 = eluf(x2); x3 = eluf(x3); }
            *(float2*)(C + (size_t)r0 * 256 + col) = make_float2(x0, x1);
            *(float2*)(C + (size_t)r1 * 256 + col) = make_float2(x2, x3);
        }
    }
}

// ---------------- fused bidirectional LSTM (recurrence only) ----------------
constexpr int LSTM_GROUPS = E_ / 8;            // 195 per direction
constexpr int LSTM_SMEM = 64 * 256 * 4 + 64 * 8 * 4;  // 67584 B

__global__ __launch_bounds__(64) void lstm_kernel(
    const float* __restrict__ gf, const float* __restrict__ gr,
    const float* __restrict__ fWhh, const float* __restrict__ rWhh,
    float* __restrict__ hfOut, float* __restrict__ hrOut) {
    extern __shared__ float sm[];
    float* Wq = sm;                       // [64 k][64 j][4 q]
    float4* hsm4 = (float4*)(sm + 64 * 256);  // [64 k][2]

    int dir; int grp;
    const float* gates; const float* Whh; float* hout;
    if (blockIdx.x < LSTM_GROUPS) {
        dir = 0; grp = blockIdx.x; gates = gf; Whh = fWhh; hout = hfOut;
    } else {
        dir = 1; grp = blockIdx.x - LSTM_GROUPS; gates = gr; Whh = rWhh; hout = hrOut;
    }
    const int j = threadIdx.x;

    for (int idx = j; idx < 64 * 256; idx += 64) {
        int k = idx >> 8;
        int rem = idx & 255;
        int jj = rem >> 2;
        int q = rem & 3;
        Wq[idx] = Whh[(q * 64 + jj) * 64 + k];
    }
    for (int i = j; i < 128; i += 64) hsm4[i] = make_float4(0.f, 0.f, 0.f, 0.f);

    const int e0 = grp * 8;
    float c[8];
#pragma unroll
    for (int e = 0; e < 8; e++) c[e] = 0.f;
    __syncthreads();

    for (int s = 0; s < T_; s++) {
        int t = dir ? (T_ - 1 - s) : s;
        float a0[8], a1[8], a2[8], a3[8];
#pragma unroll
        for (int e = 0; e < 8; e++) {
            const float* gp = gates + ((size_t)t * E_ + e0 + e) * 256;
            a0[e] = gp[j]; a1[e] = gp[64 + j]; a2[e] = gp[128 + j]; a3[e] = gp[192 + j];
        }
#pragma unroll 16
        for (int k = 0; k < 64; k++) {
            float4 w  = *(const float4*)&Wq[k * 256 + j * 4];
            float4 hA = hsm4[k * 2 + 0];
            float4 hB = hsm4[k * 2 + 1];
            float hv[8] = {hA.x, hA.y, hA.z, hA.w, hB.x, hB.y, hB.z, hB.w};
#pragma unroll
            for (int e = 0; e < 8; e++) {
                a0[e] = fmaf(hv[e], w.x, a0[e]);
                a1[e] = fmaf(hv[e], w.y, a1[e]);
                a2[e] = fmaf(hv[e], w.z, a2[e]);
                a3[e] = fmaf(hv[e], w.w, a3[e]);
            }
        }
        __syncthreads();
        float hn[8];
#pragma unroll
        for (int e = 0; e < 8; e++) {
            float iv = sigmf(a0[e]);
            float fv = sigmf(a1[e]);
            float gv = tanhf(a2[e]);
            float ov = sigmf(a3[e]);
            c[e] = fv * c[e] + iv * gv;
            hn[e] = ov * tanhf(c[e]);
        }
        hsm4[j * 2 + 0] = make_float4(hn[0], hn[1], hn[2], hn[3]);
        hsm4[j * 2 + 1] = make_float4(hn[4], hn[5], hn[6], hn[7]);
#pragma unroll
        for (int e = 0; e < 8; e++)
            hout[((size_t)t * E_ + e0 + e) * 64 + j] = hn[e];
        __syncthreads();
    }
}

// ---------------- output projection ----------------
__global__ void out_proj(const float* __restrict__ hf, const float* __restrict__ hr,
                         const float* __restrict__ priW, const float* __restrict__ prib,
                         const float* __restrict__ encW, const float* __restrict__ encb,
                         float* __restrict__ out) {
    int m = blockIdx.x * blockDim.x + threadIdx.x;
    if (m >= TE) return;
    const float* f = hf + (size_t)m * 64;
    const float* r = hr + (size_t)m * 64;
    float p0 = prib[0], p1 = prib[1], e0 = encb[0], e1 = encb[1];
#pragma unroll 8
    for (int k = 0; k < 64; k++) {
        float fv = f[k];
        p0 = fmaf(fv, priW[k], p0);
        p1 = fmaf(fv, priW[64 + k], p1);
        e0 = fmaf(fv, encW[k], e0);
        e1 = fmaf(fv, encW[128 + k], e1);
    }
#pragma unroll 8
    for (int k = 0; k < 64; k++) {
        float rv = r[k];
        e0 = fmaf(rv, encW[64 + k], e0);
        e1 = fmaf(rv, encW[192 + k], e1);
    }
    float4 o = make_float4(p0, p1, e0, e1);
    *(float4*)(out + (size_t)m * 4) = o;
}

// ---------------- host launch ----------------
extern "C" void kernel_launch(void* const* d_in, const int* in_sizes, int n_in,
                              void* d_out, int out_size) {
    const float* x     = (const float*)d_in[0];
    const int* send    = (const int*)d_in[2];
    const int* recv    = (const int*)d_in[3];
    const float* m1W1 = (const float*)d_in[4],  *m1b1 = (const float*)d_in[5];
    const float* m1W2 = (const float*)d_in[6],  *m1b2 = (const float*)d_in[7];
    const float* m2W1 = (const float*)d_in[8],  *m2b1 = (const float*)d_in[9];
    const float* m2W2 = (const float*)d_in[10], *m2b2 = (const float*)d_in[11];
    const float* m3W1 = (const float*)d_in[12], *m3b1 = (const float*)d_in[13];
    const float* m3W2 = (const float*)d_in[14], *m3b2 = (const float*)d_in[15];
    const float* m4W1 = (const float*)d_in[16], *m4b1 = (const float*)d_in[17];
    const float* m4W2 = (const float*)d_in[18], *m4b2 = (const float*)d_in[19];
    const float* fWih = (const float*)d_in[20], *fWhh = (const float*)d_in[21];
    const float* fbih = (const float*)d_in[22], *fbhh = (const float*)d_in[23];
    const float* rWih = (const float*)d_in[24], *rWhh = (const float*)d_in[25];
    const float* rbih = (const float*)d_in[26], *rbhh = (const float*)d_in[27];
    const float* encW = (const float*)d_in[28], *encb = (const float*)d_in[29];
    const float* priW = (const float*)d_in[30], *prib = (const float*)d_in[31];

    float *d_h1, *d_nbuf, *d_nsum, *d_n3, *d_e2, *d_tmp, *d_e4, *d_gf, *d_gr, *d_hf, *d_hr;
    cudaGetSymbolAddress((void**)&d_h1,   g_h1);
    cudaGetSymbolAddress((void**)&d_nbuf, g_nbuf);
    cudaGetSymbolAddress((void**)&d_nsum, g_nsum);
    cudaGetSymbolAddress((void**)&d_n3,   g_n3);
    cudaGetSymbolAddress((void**)&d_e2,   g_e2);
    cudaGetSymbolAddress((void**)&d_tmp,  g_tmp);
    cudaGetSymbolAddress((void**)&d_e4,   g_e4);
    cudaGetSymbolAddress((void**)&d_gf,   g_gf);
    cudaGetSymbolAddress((void**)&d_gr,   g_gr);
    cudaGetSymbolAddress((void**)&d_hf,   g_hf);
    cudaGetSymbolAddress((void**)&d_hr,   g_hr);

    cudaFuncSetAttribute(lstm_kernel, cudaFuncAttributeMaxDynamicSharedMemorySize, LSTM_SMEM);

    build_rlist<<<1, 64>>>(recv);

    // mlp1
    mlp1_fc1<<<TN * H_ / 256, 256>>>(x, m1W1, m1b1, d_nbuf);
    gemm_tc<0, 1, false><<<dim3(2, TN / 128), 256>>>(d_nbuf, m1W2, m1b2, nullptr, d_h1,
                                                     TN, H_, nullptr, nullptr, nullptr, nullptr);
    // mlp2 (fused node2edge gather)
    gemm_tc<1, 1, false><<<dim3(2, TE / 128), 256>>>(nullptr, m2W1, m2b1, nullptr, d_tmp,
                                                     TE, 2 * H_, send, recv, d_h1, nullptr);
    gemm_tc<0, 1, false><<<dim3(2, TE / 128), 256>>>(d_tmp, m2W2, m2b2, nullptr, d_e2,
                                                     TE, H_, nullptr, nullptr, nullptr, nullptr);
    // edge2node + mlp3
    edge2node<<<TN, 256>>>(d_e2, d_nsum);
    gemm_tc<0, 1, false><<<dim3(2, TN / 128), 256>>>(d_nsum, m3W1, m3b1, nullptr, d_nbuf,
                                                     TN, H_, nullptr, nullptr, nullptr, nullptr);
    gemm_tc<0, 1, false><<<dim3(2, TN / 128), 256>>>(d_nbuf, m3W2, m3b2, nullptr, d_n3,
                                                     TN, H_, nullptr, nullptr, nullptr, nullptr);
    // mlp4 (fused gather: n[send], n[recv], skip)
    gemm_tc<2, 1, false><<<dim3(2, TE / 128), 256>>>(nullptr, m4W1, m4b1, nullptr, d_tmp,
                                                     TE, 3 * H_, send, recv, d_n3, d_e2);
    gemm_tc<0, 1, false><<<dim3(2, TE / 128), 256>>>(d_tmp, m4W2, m4b2, nullptr, d_e4,
                                                     TE, H_, nullptr, nullptr, nullptr, nullptr);
    // LSTM input projections (time-parallel), biases folded
    gemm_tc<0, 0, true><<<dim3(2, TE / 128), 256>>>(d_e4, fWih, fbih, fbhh, d_gf,
                                                    TE, H_, nullptr, nullptr, nullptr, nullptr);
    gemm_tc<0, 0, true><<<dim3(2, TE / 128), 256>>>(d_e4, rWih, rbih, rbhh, d_gr,
                                                    TE, H_, nullptr, nullptr, nullptr, nullptr);
    // recurrence, both directions concurrently
    lstm_kernel<<<2 * LSTM_GROUPS, 64, LSTM_SMEM>>>(d_gf, d_gr, fWhh, rWhh, d_hf, d_hr);
    // outputs
    out_proj<<<TE / 256, 256>>>(d_hf, d_hr, priW, prib, encW, encb, (float*)d_out);
}